// round 8
// baseline (speedup 1.0000x reference)
#include <cuda_runtime.h>
#include <cstdint>

#define TRACKS   512
#define FEATURES 256
#define ROW_ELEMS 262145            // 1 + 512*512
#define BULK      262144            // 512*512 elements per row after the leading score

// np.float32(math.log(1e-46))
__device__ __constant__ float MASK_VAL = -105.91891427772612f;

// Cross-kernel scratch (device globals: allocation-free, allowed)
__device__ float g_scores[TRACKS];
__device__ int   g_idx;

// ---------------------------------------------------------------------------
// Kernel A: one warp per row computes dot(x[r], W) + b
// ---------------------------------------------------------------------------
__global__ void scores_kernel(const float* __restrict__ x,
                              const float* __restrict__ W,
                              const float* __restrict__ b) {
    int gwarp = (blockIdx.x * blockDim.x + threadIdx.x) >> 5;
    int lane  = threadIdx.x & 31;
    if (gwarp >= TRACKS) return;

    const float4* xr = reinterpret_cast<const float4*>(x + (size_t)gwarp * FEATURES);
    const float4* wr = reinterpret_cast<const float4*>(W);

    // FEATURES/4 = 64 float4 per row; each lane takes [lane] and [lane+32]
    float4 a0 = xr[lane];
    float4 a1 = xr[lane + 32];
    float4 w0 = __ldg(&wr[lane]);
    float4 w1 = __ldg(&wr[lane + 32]);

    float s = a0.x * w0.x + a0.y * w0.y + a0.z * w0.z + a0.w * w0.w
            + a1.x * w1.x + a1.y * w1.y + a1.z * w1.z + a1.w * w1.w;

    #pragma unroll
    for (int off = 16; off; off >>= 1)
        s += __shfl_xor_sync(0xffffffffu, s, off);

    if (lane == 0)
        g_scores[gwarp] = s + b[0];
}

// ---------------------------------------------------------------------------
// Kernel B: argmax over 512 scores, first-occurrence (smallest index) on ties
// ---------------------------------------------------------------------------
__global__ void argmax_kernel() {
    __shared__ float sv[TRACKS];
    __shared__ int   si[TRACKS];
    int t = threadIdx.x;
    sv[t] = g_scores[t];
    si[t] = t;
    __syncthreads();
    #pragma unroll
    for (int off = TRACKS / 2; off; off >>= 1) {
        if (t < off) {
            float v2 = sv[t + off];
            int   i2 = si[t + off];
            if (v2 > sv[t] || (v2 == sv[t] && i2 < si[t])) {
                sv[t] = v2;
                si[t] = i2;
            }
        }
        __syncthreads();
    }
    if (t == 0) g_idx = si[0];
}

// ---------------------------------------------------------------------------
// Kernel C: streaming fill of the (512, 262145) output.
// Row r: out[r][0] = s; out[r][1 + j] = ((j & 511) == idx) ? s*MASK : s,
// for j in [0, 262144). Rows are mutually misaligned (stride 262145 floats),
// so do a tiny scalar prologue/epilogue and float4 the aligned bulk.
// ---------------------------------------------------------------------------
__global__ void __launch_bounds__(256) fill_kernel(float* __restrict__ out) {
    const int r = blockIdx.y;
    const float s  = g_scores[r];
    const int   idx = g_idx;
    const float sm = s * MASK_VAL;

    float* p = out + (size_t)r * ROW_ELEMS;

    // p+1 is offset (r*262145 + 1) floats from out; alignment phase = (r+1) & 3
    const int a = (4 - ((r + 1) & 3)) & 3;        // scalar prologue elements
    const int e = (4 - a) & 3;                    // scalar epilogue elements
    const int N4 = (BULK - a - e) >> 2;           // aligned float4 count

    if (blockIdx.x == 0) {
        int t = threadIdx.x;
        if (t == 0) p[0] = s;
        if (t >= 1 && t <= a) {
            int j = t - 1;                        // j < 3 < 512
            p[1 + j] = (j == idx) ? sm : s;
        }
        if (t >= 4 && t < 4 + e) {
            int j = BULK - e + (t - 4);
            p[1 + j] = ((j & 511) == idx) ? sm : s;
        }
    }

    float4* q4 = reinterpret_cast<float4*>(p + 1 + a);
    const int tid    = blockIdx.x * blockDim.x + threadIdx.x;
    const int stride = gridDim.x * blockDim.x;

    for (int t = tid; t < N4; t += stride) {
        int j = a + (t << 2);
        int c = j & 511;
        float4 v;
        v.x = (c              == idx) ? sm : s;
        v.y = (((c + 1) & 511) == idx) ? sm : s;
        v.z = (((c + 2) & 511) == idx) ? sm : s;
        v.w = (((c + 3) & 511) == idx) ? sm : s;
        q4[t] = v;
    }
}

// ---------------------------------------------------------------------------
// Launch
// ---------------------------------------------------------------------------
extern "C" void kernel_launch(void* const* d_in, const int* in_sizes, int n_in,
                              void* d_out, int out_size) {
    const float* x = (const float*)d_in[0];   // (512, 256)
    const float* W = (const float*)d_in[1];   // (1, 256)
    const float* b = (const float*)d_in[2];   // (1,)
    float* out = (float*)d_out;               // (512, 262145)

    // A: 512 warps total -> 64 blocks x 256 threads (8 warps each)
    scores_kernel<<<64, 256>>>(x, W, b);
    // B: single block argmax
    argmax_kernel<<<1, TRACKS>>>();
    // C: 32 blocks per row x 512 rows, 256 threads each
    dim3 grid(32, TRACKS);
    fill_kernel<<<grid, 256>>>(out);
}

// round 9
// speedup vs baseline: 1.0039x; 1.0039x over previous
#include <cuda_runtime.h>
#include <cstdint>

#define TRACKS   512
#define FEATURES 256
#define ROW_ELEMS 262145            // 1 + 512*512
#define BULK      262144            // 512*512 elements per row after the leading score

// np.float32(math.log(1e-46))
__device__ __constant__ float MASK_VAL = -105.91891427772612f;

// Cross-kernel scratch (device globals: allocation-free, allowed)
__device__ float g_scores[TRACKS];
__device__ int   g_idx;

// ---------------------------------------------------------------------------
// Kernel A: one warp per row computes dot(x[r], W) + b
// ---------------------------------------------------------------------------
__global__ void scores_kernel(const float* __restrict__ x,
                              const float* __restrict__ W,
                              const float* __restrict__ b) {
    int gwarp = (blockIdx.x * blockDim.x + threadIdx.x) >> 5;
    int lane  = threadIdx.x & 31;
    if (gwarp >= TRACKS) return;

    const float4* xr = reinterpret_cast<const float4*>(x + (size_t)gwarp * FEATURES);
    const float4* wr = reinterpret_cast<const float4*>(W);

    // FEATURES/4 = 64 float4 per row; each lane takes [lane] and [lane+32]
    float4 a0 = xr[lane];
    float4 a1 = xr[lane + 32];
    float4 w0 = __ldg(&wr[lane]);
    float4 w1 = __ldg(&wr[lane + 32]);

    float s = a0.x * w0.x + a0.y * w0.y + a0.z * w0.z + a0.w * w0.w
            + a1.x * w1.x + a1.y * w1.y + a1.z * w1.z + a1.w * w1.w;

    #pragma unroll
    for (int off = 16; off; off >>= 1)
        s += __shfl_xor_sync(0xffffffffu, s, off);

    if (lane == 0)
        g_scores[gwarp] = s + b[0];
}

// ---------------------------------------------------------------------------
// Kernel B: argmax over 512 scores, first-occurrence (smallest index) on ties
// ---------------------------------------------------------------------------
__global__ void argmax_kernel() {
    __shared__ float sv[TRACKS];
    __shared__ int   si[TRACKS];
    int t = threadIdx.x;
    sv[t] = g_scores[t];
    si[t] = t;
    __syncthreads();
    #pragma unroll
    for (int off = TRACKS / 2; off; off >>= 1) {
        if (t < off) {
            float v2 = sv[t + off];
            int   i2 = si[t + off];
            if (v2 > sv[t] || (v2 == sv[t] && i2 < si[t])) {
                sv[t] = v2;
                si[t] = i2;
            }
        }
        __syncthreads();
    }
    if (t == 0) g_idx = si[0];
}

// ---------------------------------------------------------------------------
// Kernel C: streaming fill of the (512, 262145) output.
// Row r: out[r][0] = s; out[r][1 + j] = ((j & 511) == idx) ? s*MASK : s,
// for j in [0, 262144). Rows are mutually misaligned (stride 262145 floats),
// so do a tiny scalar prologue/epilogue and float4 the aligned bulk.
// ---------------------------------------------------------------------------
__global__ void __launch_bounds__(256) fill_kernel(float* __restrict__ out) {
    const int r = blockIdx.y;
    const float s  = g_scores[r];
    const int   idx = g_idx;
    const float sm = s * MASK_VAL;

    float* p = out + (size_t)r * ROW_ELEMS;

    // p+1 is offset (r*262145 + 1) floats from out; alignment phase = (r+1) & 3
    const int a = (4 - ((r + 1) & 3)) & 3;        // scalar prologue elements
    const int e = (4 - a) & 3;                    // scalar epilogue elements
    const int N4 = (BULK - a - e) >> 2;           // aligned float4 count

    if (blockIdx.x == 0) {
        int t = threadIdx.x;
        if (t == 0) p[0] = s;
        if (t >= 1 && t <= a) {
            int j = t - 1;                        // j < 3 < 512
            p[1 + j] = (j == idx) ? sm : s;
        }
        if (t >= 4 && t < 4 + e) {
            int j = BULK - e + (t - 4);
            p[1 + j] = ((j & 511) == idx) ? sm : s;
        }
    }

    float4* q4 = reinterpret_cast<float4*>(p + 1 + a);
    const int tid    = blockIdx.x * blockDim.x + threadIdx.x;
    const int stride = gridDim.x * blockDim.x;

    for (int t = tid; t < N4; t += stride) {
        int j = a + (t << 2);
        int c = j & 511;
        float4 v;
        v.x = (c              == idx) ? sm : s;
        v.y = (((c + 1) & 511) == idx) ? sm : s;
        v.z = (((c + 2) & 511) == idx) ? sm : s;
        v.w = (((c + 3) & 511) == idx) ? sm : s;
        q4[t] = v;
    }
}

// ---------------------------------------------------------------------------
// Launch
// ---------------------------------------------------------------------------
extern "C" void kernel_launch(void* const* d_in, const int* in_sizes, int n_in,
                              void* d_out, int out_size) {
    const float* x = (const float*)d_in[0];   // (512, 256)
    const float* W = (const float*)d_in[1];   // (1, 256)
    const float* b = (const float*)d_in[2];   // (1,)
    float* out = (float*)d_out;               // (512, 262145)

    // A: 512 warps total -> 64 blocks x 256 threads (8 warps each)
    scores_kernel<<<64, 256>>>(x, W, b);
    // B: single block argmax
    argmax_kernel<<<1, TRACKS>>>();
    // C: 32 blocks per row x 512 rows, 256 threads each
    dim3 grid(32, TRACKS);
    fill_kernel<<<grid, 256>>>(out);
}

// round 10
// speedup vs baseline: 1.0369x; 1.0329x over previous
#include <cuda_runtime.h>
#include <cstdint>

#define TRACKS   512
#define FEATURES 256
#define ROW_ELEMS 262145            // 1 + 512*512
#define BULK      262144            // 512*512 elements per row after the leading score

// np.float32(math.log(1e-46))
__device__ __constant__ float MASK_VAL = -105.91891427772612f;

// Cross-kernel scratch (device globals: allocation-free, allowed)
__device__ float g_scores[TRACKS];
__device__ unsigned long long g_pack;   // (ordered(score) << 32) | (0xFFFFFFFF - row)

// Monotone map fp32 -> u32 (order-preserving for atomicMax)
__device__ __forceinline__ unsigned int float_ordered(float f) {
    unsigned int u = __float_as_uint(f);
    return u ^ ((((int)u) >> 31) | 0x80000000u);
}

// ---------------------------------------------------------------------------
// Kernel A: one warp per row computes dot(x[r], W) + b, then folds the row
// into the global argmax via a packed atomicMax (first-occurrence tie-break:
// low word = 0xFFFFFFFF - row, so max picks the smallest row on equal scores).
// 128 blocks x 128 threads = 512 warps, spread over more SMs than 64x256.
// ---------------------------------------------------------------------------
__global__ void __launch_bounds__(128) scores_kernel(const float* __restrict__ x,
                                                     const float* __restrict__ W,
                                                     const float* __restrict__ b) {
    int gwarp = (blockIdx.x * blockDim.x + threadIdx.x) >> 5;
    int lane  = threadIdx.x & 31;
    if (gwarp >= TRACKS) return;

    const float4* xr = reinterpret_cast<const float4*>(x + (size_t)gwarp * FEATURES);
    const float4* wr = reinterpret_cast<const float4*>(W);

    // FEATURES/4 = 64 float4 per row; each lane takes [lane] and [lane+32]
    float4 a0 = xr[lane];
    float4 a1 = xr[lane + 32];
    float4 w0 = __ldg(&wr[lane]);
    float4 w1 = __ldg(&wr[lane + 32]);

    float s = a0.x * w0.x + a0.y * w0.y + a0.z * w0.z + a0.w * w0.w
            + a1.x * w1.x + a1.y * w1.y + a1.z * w1.z + a1.w * w1.w;

    #pragma unroll
    for (int off = 16; off; off >>= 1)
        s += __shfl_xor_sync(0xffffffffu, s, off);

    if (lane == 0) {
        float sc = s + b[0];
        g_scores[gwarp] = sc;
        unsigned long long pack =
            ((unsigned long long)float_ordered(sc) << 32) |
            (unsigned long long)(0xFFFFFFFFu - (unsigned int)gwarp);
        atomicMax(&g_pack, pack);
    }
}

// ---------------------------------------------------------------------------
// Kernel B: streaming fill of the (512, 262145) output.
// Row r: out[r][0] = s; out[r][1 + j] = ((j & 511) == idx) ? s*MASK : s,
// for j in [0, 262144). Rows are mutually misaligned (stride 262145 floats),
// so a tiny scalar prologue/epilogue brackets the float4 (STG.128) bulk.
// Bulk stores use __stcs (evict-first streaming) — write-once data.
// ---------------------------------------------------------------------------
__global__ void __launch_bounds__(256) fill_kernel(float* __restrict__ out) {
    const int r = blockIdx.y;
    const float s = g_scores[r];
    const unsigned long long pack = g_pack;
    const int idx = (int)(0xFFFFFFFFu - (unsigned int)(pack & 0xFFFFFFFFull));
    const float sm = s * MASK_VAL;

    float* p = out + (size_t)r * ROW_ELEMS;

    // p+1 is offset (r*262145 + 1) floats from out; alignment phase = (r+1) & 3
    const int a = (4 - ((r + 1) & 3)) & 3;        // scalar prologue elements
    const int e = (4 - a) & 3;                    // scalar epilogue elements
    const int N4 = (BULK - a - e) >> 2;           // aligned float4 count

    if (blockIdx.x == 0) {
        int t = threadIdx.x;
        if (t == 0) p[0] = s;
        if (t >= 1 && t <= a) {
            int j = t - 1;                        // j < 3 < 512
            p[1 + j] = (j == idx) ? sm : s;
        }
        if (t >= 4 && t < 4 + e) {
            int j = BULK - e + (t - 4);
            p[1 + j] = ((j & 511) == idx) ? sm : s;
        }
    }

    float4* q4 = reinterpret_cast<float4*>(p + 1 + a);
    const int tid    = blockIdx.x * blockDim.x + threadIdx.x;
    const int stride = gridDim.x * blockDim.x;

    for (int t = tid; t < N4; t += stride) {
        int j = a + (t << 2);
        int c = j & 511;
        float4 v;
        v.x = (c               == idx) ? sm : s;
        v.y = (((c + 1) & 511) == idx) ? sm : s;
        v.z = (((c + 2) & 511) == idx) ? sm : s;
        v.w = (((c + 3) & 511) == idx) ? sm : s;
        __stcs(&q4[t], v);
    }
}

// ---------------------------------------------------------------------------
// Launch: memset node (reset pack) -> fused scores+argmax -> fill
// ---------------------------------------------------------------------------
extern "C" void kernel_launch(void* const* d_in, const int* in_sizes, int n_in,
                              void* d_out, int out_size) {
    const float* x = (const float*)d_in[0];   // (512, 256)
    const float* W = (const float*)d_in[1];   // (1, 256)
    const float* b = (const float*)d_in[2];   // (1,)
    float* out = (float*)d_out;               // (512, 262145)

    // Reset the packed argmax accumulator (8-byte async memset, capturable)
    void* pack_addr = nullptr;
    cudaGetSymbolAddress(&pack_addr, g_pack);
    cudaMemsetAsync(pack_addr, 0, sizeof(unsigned long long));

    // Fused scores + argmax: 512 warps over 128 blocks
    scores_kernel<<<128, 128>>>(x, W, b);

    // Fill: 32 blocks per row x 512 rows, 256 threads each
    dim3 grid(32, TRACKS);
    fill_kernel<<<grid, 256>>>(out);
}